// round 2
// baseline (speedup 1.0000x reference)
#include <cuda_runtime.h>
#include <cuda_bf16.h>
#include <cstdio>

#define NN 100000
#define EE 500000
#define GG 2000
#define LL 5
#define EMB 300
#define H2  600
#define FEATD 256
#define EPSV 1e-5f

// ---------------- scratch (device globals; no allocs allowed) ----------------
__device__ float g_h[(size_t)NN * EMB];        // node features
__device__ float g_agg[(size_t)NN * EMB];      // aggregated messages
__device__ float g_hidden[(size_t)NN * H2];    // MLP hidden
__device__ float g_hf[(size_t)NN * FEATD];     // post-feature-proj
__device__ float g_bnsum[EMB];
__device__ float g_bnsq[EMB];
__device__ float g_pool[(size_t)GG * FEATD];
__device__ float g_cnt[GG];

// ---------------- kernels ----------------

// h = xemb1[x[:,0]] + xemb2[x[:,1]]
__global__ void embed_k(const int* __restrict__ x,
                        const float* __restrict__ e1,
                        const float* __restrict__ e2) {
    long long i = (long long)blockIdx.x * blockDim.x + threadIdx.x;
    if (i >= (long long)NN * EMB) return;
    int r = (int)(i / EMB);
    int f = (int)(i - (long long)r * EMB);
    g_h[i] = e1[x[2 * r] * EMB + f] + e2[x[2 * r + 1] * EMB + f];
}

// agg = h + self_emb   (self-loop contribution, added once per node)
__global__ void agg_init_k(const float* __restrict__ se1,
                           const float* __restrict__ se2) {
    long long i = (long long)blockIdx.x * blockDim.x + threadIdx.x;
    if (i >= (long long)NN * EMB) return;
    int f = (int)(i % EMB);
    g_agg[i] = g_h[i] + se1[f] + se2[f];
}

// one warp per edge: agg[dst] += h[src] + ee1[l][a0] + ee2[l][a1]
__global__ void scatter_k(const int* __restrict__ ei,
                          const int* __restrict__ ea,
                          const float* __restrict__ ee1l,
                          const float* __restrict__ ee2l) {
    int warp = (blockIdx.x * blockDim.x + threadIdx.x) >> 5;
    int lane = threadIdx.x & 31;
    if (warp >= EE) return;
    int s  = ei[warp];
    int d  = ei[EE + warp];
    int a0 = ea[2 * warp];
    int a1 = ea[2 * warp + 1];
    const float4* hs = (const float4*)(g_h + (size_t)s * EMB);
    const float4* t1 = (const float4*)(ee1l + (size_t)a0 * EMB);
    const float4* t2 = (const float4*)(ee2l + (size_t)a1 * EMB);
    float* ag = g_agg + (size_t)d * EMB;
    for (int j = lane; j < EMB / 4; j += 32) {    // 75 float4 per row
        float4 a = hs[j], b = t1[j], c = t2[j];
        atomicAdd(ag + 4 * j + 0, a.x + b.x + c.x);
        atomicAdd(ag + 4 * j + 1, a.y + b.y + c.y);
        atomicAdd(ag + 4 * j + 2, a.z + b.z + c.z);
        atomicAdd(ag + 4 * j + 3, a.w + b.w + c.w);
    }
}

// Tiled fp32 GEMM: C[M,Nc] = act(A[M,K] @ B[K,Nc] + bias). BM=128 BN=64 BK=8,
// 256 threads, 8x4 microtile.
template <bool RELU>
__global__ void __launch_bounds__(256)
gemm_k(const float* __restrict__ A, const float* __restrict__ B,
       const float* __restrict__ bias, float* __restrict__ C,
       int M, int K, int Ncol) {
    __shared__ float As[8][132];   // padded to kill bank conflicts
    __shared__ float Bs[8][64];
    const int bm = blockIdx.y * 128;
    const int bn = blockIdx.x * 64;
    const int tid = threadIdx.x;
    const int tx = tid & 15;       // 16 * 4 = 64 cols
    const int ty = tid >> 4;       // 16 * 8 = 128 rows

    float acc[8][4];
#pragma unroll
    for (int i = 0; i < 8; i++)
#pragma unroll
        for (int j = 0; j < 4; j++) acc[i][j] = 0.f;

    for (int k0 = 0; k0 < K; k0 += 8) {
#pragma unroll
        for (int i = 0; i < 4; i++) {
            int idx = tid * 4 + i;           // 1024 A elems
            int m = idx >> 3, k = idx & 7;
            int gm = bm + m, gk = k0 + k;
            As[k][m] = (gm < M && gk < K) ? A[(size_t)gm * K + gk] : 0.f;
        }
#pragma unroll
        for (int i = 0; i < 2; i++) {
            int idx = tid + i * 256;         // 512 B elems
            int k = idx >> 6, n = idx & 63;
            int gn = bn + n, gk = k0 + k;
            Bs[k][n] = (gn < Ncol && gk < K) ? B[(size_t)gk * Ncol + gn] : 0.f;
        }
        __syncthreads();
#pragma unroll
        for (int kk = 0; kk < 8; kk++) {
            float a[8], b[4];
            float4 a0 = *(const float4*)&As[kk][ty * 8];
            float4 a1 = *(const float4*)&As[kk][ty * 8 + 4];
            a[0]=a0.x; a[1]=a0.y; a[2]=a0.z; a[3]=a0.w;
            a[4]=a1.x; a[5]=a1.y; a[6]=a1.z; a[7]=a1.w;
            float4 b0 = *(const float4*)&Bs[kk][tx * 4];
            b[0]=b0.x; b[1]=b0.y; b[2]=b0.z; b[3]=b0.w;
#pragma unroll
            for (int i = 0; i < 8; i++)
#pragma unroll
                for (int j = 0; j < 4; j++)
                    acc[i][j] = fmaf(a[i], b[j], acc[i][j]);
        }
        __syncthreads();
    }
#pragma unroll
    for (int i = 0; i < 8; i++) {
        int gm = bm + ty * 8 + i;
        if (gm >= M) continue;
#pragma unroll
        for (int j = 0; j < 4; j++) {
            int gn = bn + tx * 4 + j;
            if (gn >= Ncol) continue;
            float v = acc[i][j] + bias[gn];
            if (RELU) v = fmaxf(v, 0.f);
            C[(size_t)gm * Ncol + gn] = v;
        }
    }
}

__global__ void bn_zero_k() {
    int i = threadIdx.x;
    if (i < EMB) { g_bnsum[i] = 0.f; g_bnsq[i] = 0.f; }
}

// per-block partial sums over 512 rows via shared atomics, then global atomics
__global__ void bn_stats_k() {
    __shared__ float ss[EMB];
    __shared__ float sq[EMB];
    for (int i = threadIdx.x; i < EMB; i += blockDim.x) { ss[i] = 0.f; sq[i] = 0.f; }
    __syncthreads();
    long long base = (long long)blockIdx.x * 512 * EMB;
    long long end  = base + (long long)512 * EMB;
    long long tot  = (long long)NN * EMB;
    if (end > tot) end = tot;
    for (long long i = base + threadIdx.x; i < end; i += blockDim.x) {
        float v = g_h[i];
        int f = (int)(i % EMB);
        atomicAdd(&ss[f], v);
        atomicAdd(&sq[f], v * v);
    }
    __syncthreads();
    for (int i = threadIdx.x; i < EMB; i += blockDim.x) {
        atomicAdd(&g_bnsum[i], ss[i]);
        atomicAdd(&g_bnsq[i], sq[i]);
    }
}

__global__ void bn_apply_k(const float* __restrict__ gamma,
                           const float* __restrict__ beta) {
    long long i = (long long)blockIdx.x * blockDim.x + threadIdx.x;
    if (i >= (long long)NN * EMB) return;
    int f = (int)(i % EMB);
    float m   = g_bnsum[f] * (1.f / NN);
    float var = g_bnsq[f] * (1.f / NN) - m * m;
    float v = (g_h[i] - m) * rsqrtf(var + EPSV) * gamma[f] + beta[f];
    g_h[i] = fmaxf(v, 0.f);
}

__global__ void pool_zero_k() {
    int i = blockIdx.x * blockDim.x + threadIdx.x;
    if (i < GG * FEATD) g_pool[i] = 0.f;
    if (i < GG) g_cnt[i] = 0.f;
}

__global__ void pool_k(const int* __restrict__ batch) {
    long long i = (long long)blockIdx.x * blockDim.x + threadIdx.x;
    if (i >= (long long)NN * FEATD) return;
    int r = (int)(i >> 8);
    int f = (int)(i & 255);
    int g = batch[r];
    atomicAdd(&g_pool[(size_t)g * FEATD + f], g_hf[i]);
    if (f == 0) atomicAdd(&g_cnt[g], 1.f);
}

__global__ void pool_div_k(float* __restrict__ out) {
    int i = blockIdx.x * blockDim.x + threadIdx.x;
    if (i >= GG * FEATD) return;
    int g = i >> 8;
    float c = fmaxf(g_cnt[g], 1.f);
    float v = g_pool[i] / c;
    out[i] = v;        // pooled output
    g_pool[i] = v;     // normalized, for the head
}

// head: relu(pooled @ pw1 + pb1) @ pw2 + pb2, one block per graph
__global__ void __launch_bounds__(128)
pred_k(const float* __restrict__ pw1, const float* __restrict__ pb1,
       const float* __restrict__ pw2, const float* __restrict__ pb2,
       float* __restrict__ out) {
    __shared__ float sp[FEATD];
    __shared__ float sh[128];
    int g = blockIdx.x, t = threadIdx.x;
    sp[t]       = g_pool[(size_t)g * FEATD + t];
    sp[t + 128] = g_pool[(size_t)g * FEATD + t + 128];
    __syncthreads();
    float acc = pb1[t];
    for (int k = 0; k < FEATD; k++) acc = fmaf(sp[k], pw1[k * 128 + t], acc);
    sh[t] = fmaxf(acc, 0.f);
    __syncthreads();
    if (t < 2) {
        float a = pb2[t];
        for (int k = 0; k < 128; k++) a = fmaf(sh[k], pw2[k * 2 + t], a);
        out[(size_t)GG * FEATD + g * 2 + t] = a;
    }
}

// ---------------- launch ----------------
extern "C" void kernel_launch(void* const* d_in, const int* in_sizes, int n_in,
                              void* d_out, int out_size) {
    const int*   x     = (const int*)d_in[0];
    const int*   ei    = (const int*)d_in[1];
    const int*   ea    = (const int*)d_in[2];
    const int*   batch = (const int*)d_in[3];
    const float* xemb1 = (const float*)d_in[4];
    const float* xemb2 = (const float*)d_in[5];
    const float* ee1   = (const float*)d_in[6];
    const float* ee2   = (const float*)d_in[7];
    const float* w1    = (const float*)d_in[8];
    const float* b1    = (const float*)d_in[9];
    const float* w2    = (const float*)d_in[10];
    const float* b2    = (const float*)d_in[11];
    const float* gamma = (const float*)d_in[12];
    const float* beta  = (const float*)d_in[13];
    const float* fw    = (const float*)d_in[14];
    const float* fb    = (const float*)d_in[15];
    const float* pw1   = (const float*)d_in[16];
    const float* pb1   = (const float*)d_in[17];
    const float* pw2   = (const float*)d_in[18];
    const float* pb2   = (const float*)d_in[19];
    float* out = (float*)d_out;

    float *p_h, *p_agg, *p_hidden, *p_hf;
    cudaGetSymbolAddress((void**)&p_h, g_h);
    cudaGetSymbolAddress((void**)&p_agg, g_agg);
    cudaGetSymbolAddress((void**)&p_hidden, g_hidden);
    cudaGetSymbolAddress((void**)&p_hf, g_hf);

    const long long nelem = (long long)NN * EMB;
    const int T = 256;
    const int gNE = (int)((nelem + T - 1) / T);

    embed_k<<<gNE, T>>>(x, xemb1, xemb2);

    for (int l = 0; l < LL; l++) {
        const float* ee1l = ee1 + (size_t)l * 6 * EMB;
        const float* ee2l = ee2 + (size_t)l * 3 * EMB;
        agg_init_k<<<gNE, T>>>(ee1l + 4 * EMB, ee2l);
        scatter_k<<<(EE * 32 + T - 1) / T, T>>>(ei, ea, ee1l, ee2l);

        dim3 grid1((H2 + 63) / 64, (NN + 127) / 128);
        gemm_k<true><<<grid1, 256>>>(p_agg, w1 + (size_t)l * EMB * H2,
                                     b1 + (size_t)l * H2, p_hidden,
                                     NN, EMB, H2);
        dim3 grid2((EMB + 63) / 64, (NN + 127) / 128);
        gemm_k<false><<<grid2, 256>>>(p_hidden, w2 + (size_t)l * H2 * EMB,
                                      b2 + (size_t)l * EMB, p_h,
                                      NN, H2, EMB);
        bn_zero_k<<<1, 320>>>();
        bn_stats_k<<<(NN + 511) / 512, 256>>>();
        bn_apply_k<<<gNE, T>>>(gamma + (size_t)l * EMB, beta + (size_t)l * EMB);
    }

    dim3 gridf((FEATD + 63) / 64, (NN + 127) / 128);
    gemm_k<false><<<gridf, 256>>>(p_h, fw, fb, p_hf, NN, EMB, FEATD);

    pool_zero_k<<<(GG * FEATD + T - 1) / T, T>>>();
    pool_k<<<(int)(((long long)NN * FEATD + T - 1) / T), T>>>(batch);
    pool_div_k<<<(GG * FEATD + T - 1) / T, T>>>(out);
    pred_k<<<GG, 128>>>(pw1, pb1, pw2, pb2, out);
}

// round 3
// speedup vs baseline: 1.4348x; 1.4348x over previous
#include <cuda_runtime.h>
#include <cuda_bf16.h>
#include <cuda_pipeline_primitives.h>
#include <mma.h>
#include <cstdio>

using namespace nvcuda;

#define NN 100000
#define EE 500000
#define GG 2000
#define LL 5
#define EMB 300
#define H2  600
#define FEATD 256
#define EPSV 1e-5f

// ---------------- scratch (device globals; no allocs allowed) ----------------
__device__ float g_h[(size_t)NN * EMB];        // node features
__device__ float g_agg[(size_t)NN * EMB];      // aggregated messages
__device__ float g_hidden[(size_t)NN * H2];    // MLP hidden
__device__ float g_hf[(size_t)NN * FEATD];     // post-feature-proj
__device__ float g_bnsum[EMB];
__device__ float g_bnsq[EMB];
__device__ float g_pool[(size_t)GG * FEATD];
__device__ float g_cnt[GG];

// ---------------- kernels ----------------

// h = xemb1[x[:,0]] + xemb2[x[:,1]]
__global__ void embed_k(const int* __restrict__ x,
                        const float* __restrict__ e1,
                        const float* __restrict__ e2) {
    long long i = (long long)blockIdx.x * blockDim.x + threadIdx.x;
    if (i >= (long long)NN * EMB) return;
    int r = (int)(i / EMB);
    int f = (int)(i - (long long)r * EMB);
    g_h[i] = e1[x[2 * r] * EMB + f] + e2[x[2 * r + 1] * EMB + f];
}

// agg = h + self_emb   (self-loop contribution, added once per node)
__global__ void agg_init_k(const float* __restrict__ se1,
                           const float* __restrict__ se2) {
    long long i = (long long)blockIdx.x * blockDim.x + threadIdx.x;
    if (i >= (long long)NN * EMB) return;
    int f = (int)(i % EMB);
    g_agg[i] = g_h[i] + se1[f] + se2[f];
}

// one warp per edge: agg[dst] += h[src] + ee1[l][a0] + ee2[l][a1]
__global__ void scatter_k(const int* __restrict__ ei,
                          const int* __restrict__ ea,
                          const float* __restrict__ ee1l,
                          const float* __restrict__ ee2l) {
    int warp = (blockIdx.x * blockDim.x + threadIdx.x) >> 5;
    int lane = threadIdx.x & 31;
    if (warp >= EE) return;
    int s  = ei[warp];
    int d  = ei[EE + warp];
    int a0 = ea[2 * warp];
    int a1 = ea[2 * warp + 1];
    const float4* hs = (const float4*)(g_h + (size_t)s * EMB);
    const float4* t1 = (const float4*)(ee1l + (size_t)a0 * EMB);
    const float4* t2 = (const float4*)(ee2l + (size_t)a1 * EMB);
    float* ag = g_agg + (size_t)d * EMB;
    for (int j = lane; j < EMB / 4; j += 32) {    // 75 float4 per row
        float4 a = hs[j], b = t1[j], c = t2[j];
        atomicAdd(ag + 4 * j + 0, a.x + b.x + c.x);
        atomicAdd(ag + 4 * j + 1, a.y + b.y + c.y);
        atomicAdd(ag + 4 * j + 2, a.z + b.z + c.z);
        atomicAdd(ag + 4 * j + 3, a.w + b.w + c.w);
    }
}

// =================== tf32 tensor-core GEMM ===================
// C[M,Ncol] = act(A[M,K] @ B[K,Ncol] + bias)
// 128x128 block tile, BK=16, 256 threads (8 warps as 4x2 of 32x64 warp tiles),
// cp.async double-buffered SMEM, wmma m16n16k8 tf32.
#define ALD 20            // A smem leading dim (128 rows x 20)
#define BLD 132           // B smem leading dim (16 rows x 132)
#define ASTG (128 * ALD)  // 2560 floats per stage
#define BSTG (16 * BLD)   // 2112 floats per stage

template <bool RELU>
__global__ void __launch_bounds__(256)
wgemm_k(const float* __restrict__ A, const float* __restrict__ B,
        const float* __restrict__ bias, float* __restrict__ C,
        int M, int K, int Ncol) {
    __shared__ float As[2 * ASTG];
    __shared__ float Bs[2 * BSTG];

    const int tid = threadIdx.x;
    const int warp_id = tid >> 5;
    const int lane = tid & 31;
    const int wm = warp_id & 3;   // 4 warp-rows of 32
    const int wn = warp_id >> 2;  // 2 warp-cols of 64
    const int bm = blockIdx.y * 128;
    const int bn = blockIdx.x * 128;

    wmma::fragment<wmma::accumulator, 16, 16, 8, float> fc[2][4];
#pragma unroll
    for (int i = 0; i < 2; i++)
#pragma unroll
        for (int j = 0; j < 4; j++) wmma::fill_fragment(fc[i][j], 0.f);

    const int KT = (K + 15) / 16;

    auto load_tiles = [&](int s, int k0) {
        // A: 128x16 = 512 float4, 2 per thread
#pragma unroll
        for (int i = 0; i < 2; i++) {
            int id = tid + i * 256;
            int row = id >> 2, kq = id & 3;
            int grow = bm + row; if (grow >= M) grow = M - 1;
            int gk = k0 + kq * 4;
            float* dst = &As[s * ASTG + row * ALD + kq * 4];
            if (gk < K) {
                __pipeline_memcpy_async(dst, &A[(size_t)grow * K + gk], 16);
            } else {
                dst[0] = 0.f; dst[1] = 0.f; dst[2] = 0.f; dst[3] = 0.f;
            }
        }
        // B: 16x128 = 512 float4, 2 per thread
#pragma unroll
        for (int i = 0; i < 2; i++) {
            int id = tid + i * 256;
            int row = id >> 5, cq = id & 31;
            int gk = k0 + row;
            int gc = bn + cq * 4; if (gc + 3 >= Ncol) gc = 0;  // clamp; garbage cols unstored
            float* dst = &Bs[s * BSTG + row * BLD + cq * 4];
            if (gk < K) {
                __pipeline_memcpy_async(dst, &B[(size_t)gk * Ncol + gc], 16);
            } else {
                dst[0] = 0.f; dst[1] = 0.f; dst[2] = 0.f; dst[3] = 0.f;
            }
        }
    };

    load_tiles(0, 0);
    __pipeline_commit();

    for (int kt = 0; kt < KT; kt++) {
        int s = kt & 1;
        bool has_next = (kt + 1 < KT);
        if (has_next) {
            load_tiles(s ^ 1, (kt + 1) * 16);
            __pipeline_commit();
        }
        __pipeline_wait_prior(has_next ? 1 : 0);
        __syncthreads();

#pragma unroll
        for (int kk = 0; kk < 16; kk += 8) {
            wmma::fragment<wmma::matrix_a, 16, 16, 8, wmma::precision::tf32,
                           wmma::row_major> fa[2];
            wmma::fragment<wmma::matrix_b, 16, 16, 8, wmma::precision::tf32,
                           wmma::row_major> fb[4];
#pragma unroll
            for (int i = 0; i < 2; i++) {
                wmma::load_matrix_sync(fa[i],
                    &As[s * ASTG + (wm * 32 + i * 16) * ALD + kk], ALD);
#pragma unroll
                for (int e = 0; e < fa[i].num_elements; e++)
                    fa[i].x[e] = wmma::__float_to_tf32(fa[i].x[e]);
            }
#pragma unroll
            for (int j = 0; j < 4; j++) {
                wmma::load_matrix_sync(fb[j],
                    &Bs[s * BSTG + kk * BLD + wn * 64 + j * 16], BLD);
#pragma unroll
                for (int e = 0; e < fb[j].num_elements; e++)
                    fb[j].x[e] = wmma::__float_to_tf32(fb[j].x[e]);
            }
#pragma unroll
            for (int i = 0; i < 2; i++)
#pragma unroll
                for (int j = 0; j < 4; j++)
                    wmma::mma_sync(fc[i][j], fa[i], fb[j], fc[i][j]);
        }
        __syncthreads();
    }

    // epilogue: stage each 16x16 tile through per-warp smem patch, guarded store
    float* patch = &As[warp_id * (16 * ALD)];  // 8 * 320 = 2560 <= 2*ASTG
#pragma unroll
    for (int i = 0; i < 2; i++) {
#pragma unroll
        for (int j = 0; j < 4; j++) {
            wmma::store_matrix_sync(patch, fc[i][j], ALD, wmma::mem_row_major);
            __syncwarp();
            int base_m = bm + wm * 32 + i * 16;
            int base_n = bn + wn * 64 + j * 16;
#pragma unroll
            for (int e = lane; e < 256; e += 32) {
                int r = e >> 4, c = e & 15;
                int gm = base_m + r, gn = base_n + c;
                if (gm < M && gn < Ncol) {
                    float v = patch[r * ALD + c] + bias[gn];
                    if (RELU) v = fmaxf(v, 0.f);
                    C[(size_t)gm * Ncol + gn] = v;
                }
            }
            __syncwarp();
        }
    }
}

__global__ void bn_zero_k() {
    int i = threadIdx.x;
    if (i < EMB) { g_bnsum[i] = 0.f; g_bnsq[i] = 0.f; }
}

// per-block partial sums over 512 rows via shared atomics, then global atomics
__global__ void bn_stats_k() {
    __shared__ float ss[EMB];
    __shared__ float sq[EMB];
    for (int i = threadIdx.x; i < EMB; i += blockDim.x) { ss[i] = 0.f; sq[i] = 0.f; }
    __syncthreads();
    long long base = (long long)blockIdx.x * 512 * EMB;
    long long end  = base + (long long)512 * EMB;
    long long tot  = (long long)NN * EMB;
    if (end > tot) end = tot;
    for (long long i = base + threadIdx.x; i < end; i += blockDim.x) {
        float v = g_h[i];
        int f = (int)(i % EMB);
        atomicAdd(&ss[f], v);
        atomicAdd(&sq[f], v * v);
    }
    __syncthreads();
    for (int i = threadIdx.x; i < EMB; i += blockDim.x) {
        atomicAdd(&g_bnsum[i], ss[i]);
        atomicAdd(&g_bnsq[i], sq[i]);
    }
}

__global__ void bn_apply_k(const float* __restrict__ gamma,
                           const float* __restrict__ beta) {
    long long i = (long long)blockIdx.x * blockDim.x + threadIdx.x;
    if (i >= (long long)NN * EMB) return;
    int f = (int)(i % EMB);
    float m   = g_bnsum[f] * (1.f / NN);
    float var = g_bnsq[f] * (1.f / NN) - m * m;
    float v = (g_h[i] - m) * rsqrtf(var + EPSV) * gamma[f] + beta[f];
    g_h[i] = fmaxf(v, 0.f);
}

__global__ void pool_zero_k() {
    int i = blockIdx.x * blockDim.x + threadIdx.x;
    if (i < GG * FEATD) g_pool[i] = 0.f;
    if (i < GG) g_cnt[i] = 0.f;
}

__global__ void pool_k(const int* __restrict__ batch) {
    long long i = (long long)blockIdx.x * blockDim.x + threadIdx.x;
    if (i >= (long long)NN * FEATD) return;
    int r = (int)(i >> 8);
    int f = (int)(i & 255);
    int g = batch[r];
    atomicAdd(&g_pool[(size_t)g * FEATD + f], g_hf[i]);
    if (f == 0) atomicAdd(&g_cnt[g], 1.f);
}

__global__ void pool_div_k(float* __restrict__ out) {
    int i = blockIdx.x * blockDim.x + threadIdx.x;
    if (i >= GG * FEATD) return;
    int g = i >> 8;
    float c = fmaxf(g_cnt[g], 1.f);
    float v = g_pool[i] / c;
    out[i] = v;        // pooled output
    g_pool[i] = v;     // normalized, for the head
}

// head: relu(pooled @ pw1 + pb1) @ pw2 + pb2, one block per graph
__global__ void __launch_bounds__(128)
pred_k(const float* __restrict__ pw1, const float* __restrict__ pb1,
       const float* __restrict__ pw2, const float* __restrict__ pb2,
       float* __restrict__ out) {
    __shared__ float sp[FEATD];
    __shared__ float sh[128];
    int g = blockIdx.x, t = threadIdx.x;
    sp[t]       = g_pool[(size_t)g * FEATD + t];
    sp[t + 128] = g_pool[(size_t)g * FEATD + t + 128];
    __syncthreads();
    float acc = pb1[t];
    for (int k = 0; k < FEATD; k++) acc = fmaf(sp[k], pw1[k * 128 + t], acc);
    sh[t] = fmaxf(acc, 0.f);
    __syncthreads();
    if (t < 2) {
        float a = pb2[t];
        for (int k = 0; k < 128; k++) a = fmaf(sh[k], pw2[k * 2 + t], a);
        out[(size_t)GG * FEATD + g * 2 + t] = a;
    }
}

// ---------------- launch ----------------
extern "C" void kernel_launch(void* const* d_in, const int* in_sizes, int n_in,
                              void* d_out, int out_size) {
    const int*   x     = (const int*)d_in[0];
    const int*   ei    = (const int*)d_in[1];
    const int*   ea    = (const int*)d_in[2];
    const int*   batch = (const int*)d_in[3];
    const float* xemb1 = (const float*)d_in[4];
    const float* xemb2 = (const float*)d_in[5];
    const float* ee1   = (const float*)d_in[6];
    const float* ee2   = (const float*)d_in[7];
    const float* w1    = (const float*)d_in[8];
    const float* b1    = (const float*)d_in[9];
    const float* w2    = (const float*)d_in[10];
    const float* b2    = (const float*)d_in[11];
    const float* gamma = (const float*)d_in[12];
    const float* beta  = (const float*)d_in[13];
    const float* fw    = (const float*)d_in[14];
    const float* fb    = (const float*)d_in[15];
    const float* pw1   = (const float*)d_in[16];
    const float* pb1   = (const float*)d_in[17];
    const float* pw2   = (const float*)d_in[18];
    const float* pb2   = (const float*)d_in[19];
    float* out = (float*)d_out;

    float *p_h, *p_agg, *p_hidden, *p_hf;
    cudaGetSymbolAddress((void**)&p_h, g_h);
    cudaGetSymbolAddress((void**)&p_agg, g_agg);
    cudaGetSymbolAddress((void**)&p_hidden, g_hidden);
    cudaGetSymbolAddress((void**)&p_hf, g_hf);

    const long long nelem = (long long)NN * EMB;
    const int T = 256;
    const int gNE = (int)((nelem + T - 1) / T);
    const int MB = (NN + 127) / 128;   // 782 row tiles

    embed_k<<<gNE, T>>>(x, xemb1, xemb2);

    for (int l = 0; l < LL; l++) {
        const float* ee1l = ee1 + (size_t)l * 6 * EMB;
        const float* ee2l = ee2 + (size_t)l * 3 * EMB;
        agg_init_k<<<gNE, T>>>(ee1l + 4 * EMB, ee2l);
        scatter_k<<<(EE * 32 + T - 1) / T, T>>>(ei, ea, ee1l, ee2l);

        dim3 grid1((H2 + 127) / 128, MB);
        wgemm_k<true><<<grid1, 256>>>(p_agg, w1 + (size_t)l * EMB * H2,
                                      b1 + (size_t)l * H2, p_hidden,
                                      NN, EMB, H2);
        dim3 grid2((EMB + 127) / 128, MB);
        wgemm_k<false><<<grid2, 256>>>(p_hidden, w2 + (size_t)l * H2 * EMB,
                                       b2 + (size_t)l * EMB, p_h,
                                       NN, H2, EMB);
        bn_zero_k<<<1, 320>>>();
        bn_stats_k<<<(NN + 511) / 512, 256>>>();
        bn_apply_k<<<gNE, T>>>(gamma + (size_t)l * EMB, beta + (size_t)l * EMB);
    }

    dim3 gridf((FEATD + 127) / 128, MB);
    wgemm_k<false><<<gridf, 256>>>(p_h, fw, fb, p_hf, NN, EMB, FEATD);

    pool_zero_k<<<(GG * FEATD + T - 1) / T, T>>>();
    pool_k<<<(int)(((long long)NN * FEATD + T - 1) / T), T>>>(batch);
    pool_div_k<<<(GG * FEATD + T - 1) / T, T>>>(out);
    pred_k<<<GG, 128>>>(pw1, pb1, pw2, pb2, out);
}

// round 4
// speedup vs baseline: 2.0681x; 1.4414x over previous
#include <cuda_runtime.h>
#include <cuda_bf16.h>
#include <cuda_pipeline_primitives.h>
#include <mma.h>
#include <cstdio>

using namespace nvcuda;

#define NN 100000
#define EE 500000
#define GG 2000
#define LL 5
#define EMB 300
#define H2  600
#define FEATD 256
#define EPSV 1e-5f
#define SRCMASK 0x1FFFF

// ---------------- scratch (device globals; no allocs allowed) ----------------
__device__ float g_h[(size_t)NN * EMB];
__device__ float g_agg[(size_t)NN * EMB];
__device__ float g_hidden[(size_t)NN * H2];
__device__ float g_hf[(size_t)NN * FEATD];
__device__ float g_bnsum[EMB];
__device__ float g_bnsq[EMB];
__device__ float g_pool[(size_t)GG * FEATD];
__device__ float g_ctab[18 * EMB];
// CSR scratch
__device__ int g_deg[NN];
__device__ int g_off[NN + 1];
__device__ int g_fill[NN];
__device__ unsigned g_edge[EE];
__device__ int g_part[128];
__device__ int g_start[GG + 1];

// ---------------- node embed ----------------
__global__ void embed_k(const int* __restrict__ x,
                        const float* __restrict__ e1,
                        const float* __restrict__ e2) {
    long long i = (long long)blockIdx.x * blockDim.x + threadIdx.x;
    if (i >= (long long)NN * EMB) return;
    int r = (int)(i / EMB);
    int f = (int)(i - (long long)r * EMB);
    g_h[i] = e1[x[2 * r] * EMB + f] + e2[x[2 * r + 1] * EMB + f];
}

// ---------------- CSR build (once per call) ----------------
__global__ void deg_zero_k() {
    int i = blockIdx.x * blockDim.x + threadIdx.x;
    if (i < NN) g_deg[i] = 0;
}
__global__ void deg_count_k(const int* __restrict__ ei) {
    int e = blockIdx.x * blockDim.x + threadIdx.x;
    if (e < EE) atomicAdd(&g_deg[ei[EE + e]], 1);
}
// block scans 1024 elems (256 thr x 4)
__global__ void scan1_k() {
    __shared__ int ssum[256];
    int tid = threadIdx.x;
    int base = blockIdx.x * 1024;
    int v[4]; int tot = 0;
#pragma unroll
    for (int i = 0; i < 4; i++) {
        int idx = base + tid * 4 + i;
        v[i] = (idx < NN) ? g_deg[idx] : 0;
        tot += v[i];
    }
    ssum[tid] = tot;
    __syncthreads();
    for (int off = 1; off < 256; off <<= 1) {
        int t = (tid >= off) ? ssum[tid - off] : 0;
        __syncthreads();
        ssum[tid] += t;
        __syncthreads();
    }
    int run = ssum[tid] - tot;   // exclusive
#pragma unroll
    for (int i = 0; i < 4; i++) {
        int idx = base + tid * 4 + i;
        if (idx < NN) g_off[idx] = run;
        run += v[i];
    }
    if (tid == 255) g_part[blockIdx.x] = ssum[255];
}
__global__ void scan2_k(int nb) {
    if (threadIdx.x == 0) {
        int run = 0;
        for (int b = 0; b < nb; b++) { int t = g_part[b]; g_part[b] = run; run += t; }
    }
}
__global__ void scan3_k() {
    int i = blockIdx.x * blockDim.x + threadIdx.x;
    if (i < NN) {
        int o = g_off[i] + g_part[i >> 10];
        g_off[i] = o;
        g_fill[i] = o;
    }
    if (i == 0) g_off[NN] = EE;
}
__global__ void fill_k(const int* __restrict__ ei, const int* __restrict__ ea) {
    int e = blockIdx.x * blockDim.x + threadIdx.x;
    if (e >= EE) return;
    int s = ei[e];
    int d = ei[EE + e];
    unsigned combo = (unsigned)(ea[2 * e] * 3 + ea[2 * e + 1]);
    int pos = atomicAdd(&g_fill[d], 1);
    g_edge[pos] = (unsigned)s | (combo << 17);
}

// ---------------- per-layer combo table ----------------
__global__ void ctab_k(const float* __restrict__ ee1l, const float* __restrict__ ee2l) {
    int i = blockIdx.x * blockDim.x + threadIdx.x;
    if (i >= 18 * EMB) return;
    int combo = i / EMB, f = i - combo * EMB;
    g_ctab[i] = ee1l[(combo / 3) * EMB + f] + ee2l[(combo % 3) * EMB + f];
}

// ---------------- gather aggregation: warp per node, no atomics -------------
__global__ void __launch_bounds__(256)
gather_k() {
    __shared__ float4 sctab[18 * EMB / 4];   // 18 combos x 75 float4
    int tid = threadIdx.x;
    const float4* gt = (const float4*)g_ctab;
    for (int i = tid; i < 18 * EMB / 4; i += 256) sctab[i] = gt[i];
    __syncthreads();
    int node = blockIdx.x * 8 + (tid >> 5);
    if (node >= NN) return;
    int lane = tid & 31;
    const float4* hn = (const float4*)(g_h + (size_t)node * EMB);
    const float4* self = &sctab[12 * 75];
    float4 a0, a1, a2;
    {
        float4 h0 = hn[lane], c0 = self[lane];
        float4 h1 = hn[lane + 32], c1 = self[lane + 32];
        a0 = make_float4(h0.x + c0.x, h0.y + c0.y, h0.z + c0.z, h0.w + c0.w);
        a1 = make_float4(h1.x + c1.x, h1.y + c1.y, h1.z + c1.z, h1.w + c1.w);
        if (lane < 11) {
            float4 h2 = hn[lane + 64], c2 = self[lane + 64];
            a2 = make_float4(h2.x + c2.x, h2.y + c2.y, h2.z + c2.z, h2.w + c2.w);
        } else a2 = make_float4(0.f, 0.f, 0.f, 0.f);
    }
    int s = g_off[node], e = g_off[node + 1];
    for (int p = s; p < e; p++) {
        unsigned pk = g_edge[p];
        const float4* hs = (const float4*)(g_h + (size_t)(pk & SRCMASK) * EMB);
        const float4* ct = &sctab[(pk >> 17) * 75];
        float4 h0 = hs[lane], c0 = ct[lane];
        a0.x += h0.x + c0.x; a0.y += h0.y + c0.y; a0.z += h0.z + c0.z; a0.w += h0.w + c0.w;
        float4 h1 = hs[lane + 32], c1 = ct[lane + 32];
        a1.x += h1.x + c1.x; a1.y += h1.y + c1.y; a1.z += h1.z + c1.z; a1.w += h1.w + c1.w;
        if (lane < 11) {
            float4 h2 = hs[lane + 64], c2 = ct[lane + 64];
            a2.x += h2.x + c2.x; a2.y += h2.y + c2.y; a2.z += h2.z + c2.z; a2.w += h2.w + c2.w;
        }
    }
    float4* ag = (float4*)(g_agg + (size_t)node * EMB);
    ag[lane] = a0;
    ag[lane + 32] = a1;
    if (lane < 11) ag[lane + 64] = a2;
}

// =================== tf32 tensor-core GEMM (unchanged) ===================
#define ALD 20
#define BLD 132
#define ASTG (128 * ALD)
#define BSTG (16 * BLD)

template <bool RELU>
__global__ void __launch_bounds__(256)
wgemm_k(const float* __restrict__ A, const float* __restrict__ B,
        const float* __restrict__ bias, float* __restrict__ C,
        int M, int K, int Ncol) {
    __shared__ float As[2 * ASTG];
    __shared__ float Bs[2 * BSTG];

    const int tid = threadIdx.x;
    const int warp_id = tid >> 5;
    const int lane = tid & 31;
    const int wm = warp_id & 3;
    const int wn = warp_id >> 2;
    const int bm = blockIdx.y * 128;
    const int bn = blockIdx.x * 128;

    wmma::fragment<wmma::accumulator, 16, 16, 8, float> fc[2][4];
#pragma unroll
    for (int i = 0; i < 2; i++)
#pragma unroll
        for (int j = 0; j < 4; j++) wmma::fill_fragment(fc[i][j], 0.f);

    const int KT = (K + 15) / 16;

    auto load_tiles = [&](int s, int k0) {
#pragma unroll
        for (int i = 0; i < 2; i++) {
            int id = tid + i * 256;
            int row = id >> 2, kq = id & 3;
            int grow = bm + row; if (grow >= M) grow = M - 1;
            int gk = k0 + kq * 4;
            float* dst = &As[s * ASTG + row * ALD + kq * 4];
            if (gk < K) {
                __pipeline_memcpy_async(dst, &A[(size_t)grow * K + gk], 16);
            } else {
                dst[0] = 0.f; dst[1] = 0.f; dst[2] = 0.f; dst[3] = 0.f;
            }
        }
#pragma unroll
        for (int i = 0; i < 2; i++) {
            int id = tid + i * 256;
            int row = id >> 5, cq = id & 31;
            int gk = k0 + row;
            int gc = bn + cq * 4; if (gc + 3 >= Ncol) gc = 0;
            float* dst = &Bs[s * BSTG + row * BLD + cq * 4];
            if (gk < K) {
                __pipeline_memcpy_async(dst, &B[(size_t)gk * Ncol + gc], 16);
            } else {
                dst[0] = 0.f; dst[1] = 0.f; dst[2] = 0.f; dst[3] = 0.f;
            }
        }
    };

    load_tiles(0, 0);
    __pipeline_commit();

    for (int kt = 0; kt < KT; kt++) {
        int s = kt & 1;
        bool has_next = (kt + 1 < KT);
        if (has_next) {
            load_tiles(s ^ 1, (kt + 1) * 16);
            __pipeline_commit();
        }
        __pipeline_wait_prior(has_next ? 1 : 0);
        __syncthreads();

#pragma unroll
        for (int kk = 0; kk < 16; kk += 8) {
            wmma::fragment<wmma::matrix_a, 16, 16, 8, wmma::precision::tf32,
                           wmma::row_major> fa[2];
            wmma::fragment<wmma::matrix_b, 16, 16, 8, wmma::precision::tf32,
                           wmma::row_major> fb[4];
#pragma unroll
            for (int i = 0; i < 2; i++) {
                wmma::load_matrix_sync(fa[i],
                    &As[s * ASTG + (wm * 32 + i * 16) * ALD + kk], ALD);
#pragma unroll
                for (int e = 0; e < fa[i].num_elements; e++)
                    fa[i].x[e] = wmma::__float_to_tf32(fa[i].x[e]);
            }
#pragma unroll
            for (int j = 0; j < 4; j++) {
                wmma::load_matrix_sync(fb[j],
                    &Bs[s * BSTG + kk * BLD + wn * 64 + j * 16], BLD);
#pragma unroll
                for (int e = 0; e < fb[j].num_elements; e++)
                    fb[j].x[e] = wmma::__float_to_tf32(fb[j].x[e]);
            }
#pragma unroll
            for (int i = 0; i < 2; i++)
#pragma unroll
                for (int j = 0; j < 4; j++)
                    wmma::mma_sync(fc[i][j], fa[i], fb[j], fc[i][j]);
        }
        __syncthreads();
    }

    float* patch = &As[warp_id * (16 * ALD)];
#pragma unroll
    for (int i = 0; i < 2; i++) {
#pragma unroll
        for (int j = 0; j < 4; j++) {
            wmma::store_matrix_sync(patch, fc[i][j], ALD, wmma::mem_row_major);
            __syncwarp();
            int base_m = bm + wm * 32 + i * 16;
            int base_n = bn + wn * 64 + j * 16;
#pragma unroll
            for (int e = lane; e < 256; e += 32) {
                int r = e >> 4, c = e & 15;
                int gm = base_m + r, gn = base_n + c;
                if (gm < M && gn < Ncol) {
                    float v = patch[r * ALD + c] + bias[gn];
                    if (RELU) v = fmaxf(v, 0.f);
                    C[(size_t)gm * Ncol + gn] = v;
                }
            }
            __syncwarp();
        }
    }
}

// ---------------- BatchNorm ----------------
__global__ void bn_zero_k() {
    int i = threadIdx.x;
    if (i < EMB) { g_bnsum[i] = 0.f; g_bnsq[i] = 0.f; }
}
// thread-per-column register reduction over a 512-row chunk
__global__ void bn_stats_k() {
    int f = threadIdx.x;
    if (f >= EMB) return;
    long long r0 = (long long)blockIdx.x * 512;
    long long r1 = r0 + 512; if (r1 > NN) r1 = NN;
    float s = 0.f, q = 0.f;
    for (long long r = r0; r < r1; r++) {
        float v = g_h[r * EMB + f];
        s += v; q += v * v;
    }
    atomicAdd(&g_bnsum[f], s);
    atomicAdd(&g_bnsq[f], q);
}
__global__ void bn_apply_k(const float* __restrict__ gamma,
                           const float* __restrict__ beta) {
    long long i = (long long)blockIdx.x * blockDim.x + threadIdx.x;
    if (i >= (long long)NN * EMB) return;
    int f = (int)(i % EMB);
    float m   = g_bnsum[f] * (1.f / NN);
    float var = g_bnsq[f] * (1.f / NN) - m * m;
    float v = (g_h[i] - m) * rsqrtf(var + EPSV) * gamma[f] + beta[f];
    g_h[i] = fmaxf(v, 0.f);
}

// ---------------- pooling (sorted batch -> boundaries, no atomics) ----------
__global__ void start_init_k() {
    int g = blockIdx.x * blockDim.x + threadIdx.x;
    if (g <= GG) g_start[g] = NN;
}
__global__ void bounds_k(const int* __restrict__ batch) {
    int r = blockIdx.x * blockDim.x + threadIdx.x;
    if (r >= NN) return;
    int b = batch[r];
    int pb = (r == 0) ? -1 : batch[r - 1];
    for (int g = pb + 1; g <= b; g++) g_start[g] = r;
}
__global__ void __launch_bounds__(256)
pool_g_k(float* __restrict__ out) {
    int g = blockIdx.x, f = threadIdx.x;
    int s = g_start[g], e = g_start[g + 1];
    float acc = 0.f;
    for (int r = s; r < e; r++) acc += g_hf[(size_t)r * FEATD + f];
    float c = fmaxf((float)(e - s), 1.f);
    float v = acc / c;
    out[(size_t)g * FEATD + f] = v;
    g_pool[(size_t)g * FEATD + f] = v;
}

// head: relu(pooled @ pw1 + pb1) @ pw2 + pb2
__global__ void __launch_bounds__(128)
pred_k(const float* __restrict__ pw1, const float* __restrict__ pb1,
       const float* __restrict__ pw2, const float* __restrict__ pb2,
       float* __restrict__ out) {
    __shared__ float sp[FEATD];
    __shared__ float sh[128];
    int g = blockIdx.x, t = threadIdx.x;
    sp[t]       = g_pool[(size_t)g * FEATD + t];
    sp[t + 128] = g_pool[(size_t)g * FEATD + t + 128];
    __syncthreads();
    float acc = pb1[t];
    for (int k = 0; k < FEATD; k++) acc = fmaf(sp[k], pw1[k * 128 + t], acc);
    sh[t] = fmaxf(acc, 0.f);
    __syncthreads();
    if (t < 2) {
        float a = pb2[t];
        for (int k = 0; k < 128; k++) a = fmaf(sh[k], pw2[k * 2 + t], a);
        out[(size_t)GG * FEATD + g * 2 + t] = a;
    }
}

// ---------------- launch ----------------
extern "C" void kernel_launch(void* const* d_in, const int* in_sizes, int n_in,
                              void* d_out, int out_size) {
    const int*   x     = (const int*)d_in[0];
    const int*   ei    = (const int*)d_in[1];
    const int*   ea    = (const int*)d_in[2];
    const int*   batch = (const int*)d_in[3];
    const float* xemb1 = (const float*)d_in[4];
    const float* xemb2 = (const float*)d_in[5];
    const float* ee1   = (const float*)d_in[6];
    const float* ee2   = (const float*)d_in[7];
    const float* w1    = (const float*)d_in[8];
    const float* b1    = (const float*)d_in[9];
    const float* w2    = (const float*)d_in[10];
    const float* b2    = (const float*)d_in[11];
    const float* gamma = (const float*)d_in[12];
    const float* beta  = (const float*)d_in[13];
    const float* fw    = (const float*)d_in[14];
    const float* fb    = (const float*)d_in[15];
    const float* pw1   = (const float*)d_in[16];
    const float* pb1   = (const float*)d_in[17];
    const float* pw2   = (const float*)d_in[18];
    const float* pb2   = (const float*)d_in[19];
    float* out = (float*)d_out;

    float *p_h, *p_agg, *p_hidden, *p_hf;
    cudaGetSymbolAddress((void**)&p_h, g_h);
    cudaGetSymbolAddress((void**)&p_agg, g_agg);
    cudaGetSymbolAddress((void**)&p_hidden, g_hidden);
    cudaGetSymbolAddress((void**)&p_hf, g_hf);

    const long long nelem = (long long)NN * EMB;
    const int T = 256;
    const int gNE = (int)((nelem + T - 1) / T);
    const int MB = (NN + 127) / 128;
    const int NB_SCAN = (NN + 1023) / 1024;

    embed_k<<<gNE, T>>>(x, xemb1, xemb2);

    // CSR build (once)
    deg_zero_k<<<(NN + T - 1) / T, T>>>();
    deg_count_k<<<(EE + T - 1) / T, T>>>(ei);
    scan1_k<<<NB_SCAN, 256>>>();
    scan2_k<<<1, 32>>>(NB_SCAN);
    scan3_k<<<(NN + T - 1) / T, T>>>();
    fill_k<<<(EE + T - 1) / T, T>>>(ei, ea);

    for (int l = 0; l < LL; l++) {
        const float* ee1l = ee1 + (size_t)l * 6 * EMB;
        const float* ee2l = ee2 + (size_t)l * 3 * EMB;
        ctab_k<<<(18 * EMB + T - 1) / T, T>>>(ee1l, ee2l);
        gather_k<<<(NN + 7) / 8, 256>>>();

        dim3 grid1((H2 + 127) / 128, MB);
        wgemm_k<true><<<grid1, 256>>>(p_agg, w1 + (size_t)l * EMB * H2,
                                      b1 + (size_t)l * H2, p_hidden,
                                      NN, EMB, H2);
        dim3 grid2((EMB + 127) / 128, MB);
        wgemm_k<false><<<grid2, 256>>>(p_hidden, w2 + (size_t)l * H2 * EMB,
                                       b2 + (size_t)l * EMB, p_h,
                                       NN, H2, EMB);
        bn_zero_k<<<1, 320>>>();
        bn_stats_k<<<(NN + 511) / 512, 320>>>();
        bn_apply_k<<<gNE, T>>>(gamma + (size_t)l * EMB, beta + (size_t)l * EMB);
    }

    dim3 gridf((FEATD + 127) / 128, MB);
    wgemm_k<false><<<gridf, 256>>>(p_h, fw, fb, p_hf, NN, EMB, FEATD);

    start_init_k<<<(GG + 1 + T - 1) / T, T>>>();
    bounds_k<<<(NN + T - 1) / T, T>>>(batch);
    pool_g_k<<<GG, FEATD>>>(out);
    pred_k<<<GG, 128>>>(pw1, pb1, pw2, pb2, out);
}

// round 5
// speedup vs baseline: 2.1388x; 1.0341x over previous
#include <cuda_runtime.h>
#include <cuda_bf16.h>
#include <cuda_pipeline_primitives.h>
#include <mma.h>
#include <cstdio>

using namespace nvcuda;

#define NN 100000
#define EE 500000
#define GG 2000
#define LL 5
#define EMB 300
#define H2  600
#define FEATD 256
#define EPSV 1e-5f
#define SRCMASK 0x1FFFF

// ---------------- scratch (device globals; no allocs allowed) ----------------
__device__ float g_h[(size_t)NN * EMB];
__device__ float g_agg[(size_t)NN * EMB];
__device__ float g_hidden[(size_t)NN * H2];
__device__ float g_hf[(size_t)NN * FEATD];
__device__ float g_bnsum[EMB];
__device__ float g_bnsq[EMB];
__device__ float g_bnscale[EMB];
__device__ float g_bnshift[EMB];
__device__ float g_pool[(size_t)GG * FEATD];
__device__ float g_ctab[18 * EMB];
__device__ float g_wbuf[EMB * H2];     // tf32-rounded weight staging
// CSR scratch
__device__ int g_deg[NN];
__device__ int g_off[NN + 1];
__device__ int g_fill[NN];
__device__ unsigned g_edge[EE];
__device__ int g_part[128];
__device__ int g_start[GG + 1];

// ---------------- node embed ----------------
__global__ void embed_k(const int* __restrict__ x,
                        const float* __restrict__ e1,
                        const float* __restrict__ e2) {
    long long i = (long long)blockIdx.x * blockDim.x + threadIdx.x;
    if (i >= (long long)NN * EMB) return;
    int r = (int)(i / EMB);
    int f = (int)(i - (long long)r * EMB);
    g_h[i] = e1[x[2 * r] * EMB + f] + e2[x[2 * r + 1] * EMB + f];
}

// ---------------- CSR build (once per call) ----------------
__global__ void deg_zero_k() {
    int i = blockIdx.x * blockDim.x + threadIdx.x;
    if (i < NN) g_deg[i] = 0;
}
__global__ void deg_count_k(const int* __restrict__ ei) {
    int e = blockIdx.x * blockDim.x + threadIdx.x;
    if (e < EE) atomicAdd(&g_deg[ei[EE + e]], 1);
}
__global__ void scan1_k() {
    __shared__ int ssum[256];
    int tid = threadIdx.x;
    int base = blockIdx.x * 1024;
    int v[4]; int tot = 0;
#pragma unroll
    for (int i = 0; i < 4; i++) {
        int idx = base + tid * 4 + i;
        v[i] = (idx < NN) ? g_deg[idx] : 0;
        tot += v[i];
    }
    ssum[tid] = tot;
    __syncthreads();
    for (int off = 1; off < 256; off <<= 1) {
        int t = (tid >= off) ? ssum[tid - off] : 0;
        __syncthreads();
        ssum[tid] += t;
        __syncthreads();
    }
    int run = ssum[tid] - tot;
#pragma unroll
    for (int i = 0; i < 4; i++) {
        int idx = base + tid * 4 + i;
        if (idx < NN) g_off[idx] = run;
        run += v[i];
    }
    if (tid == 255) g_part[blockIdx.x] = ssum[255];
}
__global__ void scan2_k(int nb) {
    if (threadIdx.x == 0) {
        int run = 0;
        for (int b = 0; b < nb; b++) { int t = g_part[b]; g_part[b] = run; run += t; }
    }
}
__global__ void scan3_k() {
    int i = blockIdx.x * blockDim.x + threadIdx.x;
    if (i < NN) {
        int o = g_off[i] + g_part[i >> 10];
        g_off[i] = o;
        g_fill[i] = o;
    }
    if (i == 0) g_off[NN] = EE;
}
__global__ void fill_k(const int* __restrict__ ei, const int* __restrict__ ea) {
    int e = blockIdx.x * blockDim.x + threadIdx.x;
    if (e >= EE) return;
    int s = ei[e];
    int d = ei[EE + e];
    unsigned combo = (unsigned)(ea[2 * e] * 3 + ea[2 * e + 1]);
    int pos = atomicAdd(&g_fill[d], 1);
    g_edge[pos] = (unsigned)s | (combo << 17);
}

// ---------------- per-layer combo table ----------------
__global__ void ctab_k(const float* __restrict__ ee1l, const float* __restrict__ ee2l) {
    int i = blockIdx.x * blockDim.x + threadIdx.x;
    if (i >= 18 * EMB) return;
    int combo = i / EMB, f = i - combo * EMB;
    g_ctab[i] = ee1l[(combo / 3) * EMB + f] + ee2l[(combo % 3) * EMB + f];
}

// ---------------- weight tf32 pre-round ----------------
__global__ void round_k(const float* __restrict__ src, int n) {
    int i = blockIdx.x * blockDim.x + threadIdx.x;
    if (i < n) g_wbuf[i] = wmma::__float_to_tf32(src[i]);
}

// ---------------- gather: warp/node, BN+ReLU fused on reads, tf32-rounded out
template <bool BN>
__global__ void __launch_bounds__(256)
gather_k() {
    __shared__ float4 sctab[18 * EMB / 4];
    __shared__ float4 ssc[EMB / 4 + 1];
    __shared__ float4 ssh[EMB / 4 + 1];
    int tid = threadIdx.x;
    const float4* gt = (const float4*)g_ctab;
    for (int i = tid; i < 18 * EMB / 4; i += 256) sctab[i] = gt[i];
    if (BN) {
        const float4* sc = (const float4*)g_bnscale;
        const float4* sh = (const float4*)g_bnshift;
        for (int i = tid; i < EMB / 4; i += 256) { ssc[i] = sc[i]; ssh[i] = sh[i]; }
    }
    __syncthreads();
    int node = blockIdx.x * 8 + (tid >> 5);
    if (node >= NN) return;
    int lane = tid & 31;
    int i0 = lane, i1 = lane + 32, i2 = lane + 64;   // i2 valid iff lane<11
    float4 sc0, sc1, sc2, sh0, sh1, sh2;
    if (BN) {
        sc0 = ssc[i0]; sh0 = ssh[i0];
        sc1 = ssc[i1]; sh1 = ssh[i1];
        if (lane < 11) { sc2 = ssc[i2]; sh2 = ssh[i2]; }
    }
    auto norm = [&](float4 h, const float4& sc, const float4& sh) -> float4 {
        if (!BN) return h;
        return make_float4(fmaxf(fmaf(h.x, sc.x, sh.x), 0.f),
                           fmaxf(fmaf(h.y, sc.y, sh.y), 0.f),
                           fmaxf(fmaf(h.z, sc.z, sh.z), 0.f),
                           fmaxf(fmaf(h.w, sc.w, sh.w), 0.f));
    };
    float4 a0, a1, a2;
    {
        const float4* hn = (const float4*)(g_h + (size_t)node * EMB);
        const float4* self = &sctab[12 * 75];
        float4 h0 = norm(hn[i0], sc0, sh0), c0 = self[i0];
        float4 h1 = norm(hn[i1], sc1, sh1), c1 = self[i1];
        a0 = make_float4(h0.x + c0.x, h0.y + c0.y, h0.z + c0.z, h0.w + c0.w);
        a1 = make_float4(h1.x + c1.x, h1.y + c1.y, h1.z + c1.z, h1.w + c1.w);
        a2 = make_float4(0.f, 0.f, 0.f, 0.f);
        if (lane < 11) {
            float4 h2 = norm(hn[i2], sc2, sh2), c2 = self[i2];
            a2 = make_float4(h2.x + c2.x, h2.y + c2.y, h2.z + c2.z, h2.w + c2.w);
        }
    }
    int s = g_off[node], e = g_off[node + 1];
    int p = s;
    for (; p + 1 < e; p += 2) {   // 2-edge unroll: 6 gathers in flight
        unsigned pka = g_edge[p], pkb = g_edge[p + 1];
        const float4* ha = (const float4*)(g_h + (size_t)(pka & SRCMASK) * EMB);
        const float4* hb = (const float4*)(g_h + (size_t)(pkb & SRCMASK) * EMB);
        const float4* ca = &sctab[(pka >> 17) * 75];
        const float4* cb = &sctab[(pkb >> 17) * 75];
        float4 ha0 = ha[i0], hb0 = hb[i0];
        float4 ha1 = ha[i1], hb1 = hb[i1];
        float4 ha2, hb2;
        if (lane < 11) { ha2 = ha[i2]; hb2 = hb[i2]; }
        ha0 = norm(ha0, sc0, sh0); hb0 = norm(hb0, sc0, sh0);
        ha1 = norm(ha1, sc1, sh1); hb1 = norm(hb1, sc1, sh1);
        float4 c;
        c = ca[i0]; a0.x += ha0.x + c.x; a0.y += ha0.y + c.y; a0.z += ha0.z + c.z; a0.w += ha0.w + c.w;
        c = cb[i0]; a0.x += hb0.x + c.x; a0.y += hb0.y + c.y; a0.z += hb0.z + c.z; a0.w += hb0.w + c.w;
        c = ca[i1]; a1.x += ha1.x + c.x; a1.y += ha1.y + c.y; a1.z += ha1.z + c.z; a1.w += ha1.w + c.w;
        c = cb[i1]; a1.x += hb1.x + c.x; a1.y += hb1.y + c.y; a1.z += hb1.z + c.z; a1.w += hb1.w + c.w;
        if (lane < 11) {
            ha2 = norm(ha2, sc2, sh2); hb2 = norm(hb2, sc2, sh2);
            c = ca[i2]; a2.x += ha2.x + c.x; a2.y += ha2.y + c.y; a2.z += ha2.z + c.z; a2.w += ha2.w + c.w;
            c = cb[i2]; a2.x += hb2.x + c.x; a2.y += hb2.y + c.y; a2.z += hb2.z + c.z; a2.w += hb2.w + c.w;
        }
    }
    for (; p < e; p++) {
        unsigned pk = g_edge[p];
        const float4* hs = (const float4*)(g_h + (size_t)(pk & SRCMASK) * EMB);
        const float4* ct = &sctab[(pk >> 17) * 75];
        float4 h0 = norm(hs[i0], sc0, sh0), c0 = ct[i0];
        a0.x += h0.x + c0.x; a0.y += h0.y + c0.y; a0.z += h0.z + c0.z; a0.w += h0.w + c0.w;
        float4 h1 = norm(hs[i1], sc1, sh1), c1 = ct[i1];
        a1.x += h1.x + c1.x; a1.y += h1.y + c1.y; a1.z += h1.z + c1.z; a1.w += h1.w + c1.w;
        if (lane < 11) {
            float4 h2 = norm(hs[i2], sc2, sh2), c2 = ct[i2];
            a2.x += h2.x + c2.x; a2.y += h2.y + c2.y; a2.z += h2.z + c2.z; a2.w += h2.w + c2.w;
        }
    }
    auto rnd4 = [](float4 v) {
        return make_float4(wmma::__float_to_tf32(v.x), wmma::__float_to_tf32(v.y),
                           wmma::__float_to_tf32(v.z), wmma::__float_to_tf32(v.w));
    };
    float4* ag = (float4*)(g_agg + (size_t)node * EMB);
    ag[i0] = rnd4(a0);
    ag[i1] = rnd4(a1);
    if (lane < 11) ag[i2] = rnd4(a2);
}

// =================== tf32 tensor-core GEMM (operands pre-rounded) ===========
#define ALD 20
#define BLD 132
#define ASTG (128 * ALD)
#define BSTG (16 * BLD)

template <bool RELU, bool STATS, bool ROUND_OUT>
__global__ void __launch_bounds__(256)
wgemm_k(const float* __restrict__ A, const float* __restrict__ B,
        const float* __restrict__ bias, float* __restrict__ C,
        int M, int K, int Ncol) {
    __shared__ float As[2 * ASTG];
    __shared__ float Bs[2 * BSTG];

    const int tid = threadIdx.x;
    const int warp_id = tid >> 5;
    const int lane = tid & 31;
    const int wm = warp_id & 3;
    const int wn = warp_id >> 2;
    const int bm = blockIdx.y * 128;
    const int bn = blockIdx.x * 128;

    wmma::fragment<wmma::accumulator, 16, 16, 8, float> fc[2][4];
#pragma unroll
    for (int i = 0; i < 2; i++)
#pragma unroll
        for (int j = 0; j < 4; j++) wmma::fill_fragment(fc[i][j], 0.f);

    const int KT = (K + 15) / 16;

    auto load_tiles = [&](int s, int k0) {
#pragma unroll
        for (int i = 0; i < 2; i++) {
            int id = tid + i * 256;
            int row = id >> 2, kq = id & 3;
            int grow = bm + row; if (grow >= M) grow = M - 1;
            int gk = k0 + kq * 4;
            float* dst = &As[s * ASTG + row * ALD + kq * 4];
            if (gk < K) {
                __pipeline_memcpy_async(dst, &A[(size_t)grow * K + gk], 16);
            } else {
                dst[0] = 0.f; dst[1] = 0.f; dst[2] = 0.f; dst[3] = 0.f;
            }
        }
#pragma unroll
        for (int i = 0; i < 2; i++) {
            int id = tid + i * 256;
            int row = id >> 5, cq = id & 31;
            int gk = k0 + row;
            int gc = bn + cq * 4; if (gc + 3 >= Ncol) gc = 0;
            float* dst = &Bs[s * BSTG + row * BLD + cq * 4];
            if (gk < K) {
                __pipeline_memcpy_async(dst, &B[(size_t)gk * Ncol + gc], 16);
            } else {
                dst[0] = 0.f; dst[1] = 0.f; dst[2] = 0.f; dst[3] = 0.f;
            }
        }
    };

    load_tiles(0, 0);
    __pipeline_commit();

    for (int kt = 0; kt < KT; kt++) {
        int s = kt & 1;
        bool has_next = (kt + 1 < KT);
        if (has_next) {
            load_tiles(s ^ 1, (kt + 1) * 16);
            __pipeline_commit();
        }
        __pipeline_wait_prior(has_next ? 1 : 0);
        __syncthreads();

#pragma unroll
        for (int kk = 0; kk < 16; kk += 8) {
            wmma::fragment<wmma::matrix_a, 16, 16, 8, wmma::precision::tf32,
                           wmma::row_major> fa[2];
            wmma::fragment<wmma::matrix_b, 16, 16, 8, wmma::precision::tf32,
                           wmma::row_major> fb[4];
#pragma unroll
            for (int i = 0; i < 2; i++)
                wmma::load_matrix_sync(fa[i],
                    &As[s * ASTG + (wm * 32 + i * 16) * ALD + kk], ALD);
#pragma unroll
            for (int j = 0; j < 4; j++)
                wmma::load_matrix_sync(fb[j],
                    &Bs[s * BSTG + kk * BLD + wn * 64 + j * 16], BLD);
#pragma unroll
            for (int i = 0; i < 2; i++)
#pragma unroll
                for (int j = 0; j < 4; j++)
                    wmma::mma_sync(fc[i][j], fa[i], fb[j], fc[i][j]);
        }
        __syncthreads();
    }

    float ssum[4], ssq[4];
    if (STATS) {
#pragma unroll
        for (int j = 0; j < 4; j++) { ssum[j] = 0.f; ssq[j] = 0.f; }
    }
    float* patch = &As[warp_id * (16 * ALD)];
#pragma unroll
    for (int i = 0; i < 2; i++) {
#pragma unroll
        for (int j = 0; j < 4; j++) {
            wmma::store_matrix_sync(patch, fc[i][j], ALD, wmma::mem_row_major);
            __syncwarp();
            int base_m = bm + wm * 32 + i * 16;
            int base_n = bn + wn * 64 + j * 16;
#pragma unroll
            for (int e = lane; e < 256; e += 32) {
                int r = e >> 4, c = e & 15;
                int gm = base_m + r, gn = base_n + c;
                if (gm < M && gn < Ncol) {
                    float v = patch[r * ALD + c] + bias[gn];
                    if (RELU) v = fmaxf(v, 0.f);
                    if (STATS) { ssum[j] += v; ssq[j] += v * v; }
                    if (ROUND_OUT) v = wmma::__float_to_tf32(v);
                    C[(size_t)gm * Ncol + gn] = v;
                }
            }
            __syncwarp();
        }
    }
    if (STATS) {
#pragma unroll
        for (int j = 0; j < 4; j++) {
            int gn = bn + wn * 64 + j * 16 + (lane & 15);
            if (gn < Ncol) {
                atomicAdd(&g_bnsum[gn], ssum[j]);
                atomicAdd(&g_bnsq[gn], ssq[j]);
            }
        }
    }
}

// ---------------- BatchNorm ----------------
__global__ void bn_zero_k() {
    int i = threadIdx.x;
    if (i < EMB) { g_bnsum[i] = 0.f; g_bnsq[i] = 0.f; }
}
__global__ void bnfin_k(const float* __restrict__ gamma,
                        const float* __restrict__ beta) {
    int f = threadIdx.x;
    if (f >= EMB) return;
    float m   = g_bnsum[f] * (1.f / NN);
    float var = g_bnsq[f] * (1.f / NN) - m * m;
    float sc  = rsqrtf(var + EPSV) * gamma[f];
    g_bnscale[f] = sc;
    g_bnshift[f] = beta[f] - m * sc;
}
// final layer: apply BN+relu to h in place, round to tf32 for feat GEMM
__global__ void bn_apply_k() {
    long long i = (long long)blockIdx.x * blockDim.x + threadIdx.x;
    if (i >= (long long)NN * EMB) return;
    int f = (int)(i % EMB);
    float v = fmaxf(fmaf(g_h[i], g_bnscale[f], g_bnshift[f]), 0.f);
    g_h[i] = wmma::__float_to_tf32(v);
}

// ---------------- pooling ----------------
__global__ void start_init_k() {
    int g = blockIdx.x * blockDim.x + threadIdx.x;
    if (g <= GG) g_start[g] = NN;
}
__global__ void bounds_k(const int* __restrict__ batch) {
    int r = blockIdx.x * blockDim.x + threadIdx.x;
    if (r >= NN) return;
    int b = batch[r];
    int pb = (r == 0) ? -1 : batch[r - 1];
    for (int g = pb + 1; g <= b; g++) g_start[g] = r;
}
__global__ void __launch_bounds__(256)
pool_g_k(float* __restrict__ out) {
    int g = blockIdx.x, f = threadIdx.x;
    int s = g_start[g], e = g_start[g + 1];
    float acc = 0.f;
    for (int r = s; r < e; r++) acc += g_hf[(size_t)r * FEATD + f];
    float c = fmaxf((float)(e - s), 1.f);
    float v = acc / c;
    out[(size_t)g * FEATD + f] = v;
    g_pool[(size_t)g * FEATD + f] = v;
}

// head
__global__ void __launch_bounds__(128)
pred_k(const float* __restrict__ pw1, const float* __restrict__ pb1,
       const float* __restrict__ pw2, const float* __restrict__ pb2,
       float* __restrict__ out) {
    __shared__ float sp[FEATD];
    __shared__ float sh[128];
    int g = blockIdx.x, t = threadIdx.x;
    sp[t]       = g_pool[(size_t)g * FEATD + t];
    sp[t + 128] = g_pool[(size_t)g * FEATD + t + 128];
    __syncthreads();
    float acc = pb1[t];
    for (int k = 0; k < FEATD; k++) acc = fmaf(sp[k], pw1[k * 128 + t], acc);
    sh[t] = fmaxf(acc, 0.f);
    __syncthreads();
    if (t < 2) {
        float a = pb2[t];
        for (int k = 0; k < 128; k++) a = fmaf(sh[k], pw2[k * 2 + t], a);
        out[(size_t)GG * FEATD + g * 2 + t] = a;
    }
}

// ---------------- launch ----------------
extern "C" void kernel_launch(void* const* d_in, const int* in_sizes, int n_in,
                              void* d_out, int out_size) {
    const int*   x     = (const int*)d_in[0];
    const int*   ei    = (const int*)d_in[1];
    const int*   ea    = (const int*)d_in[2];
    const int*   batch = (const int*)d_in[3];
    const float* xemb1 = (const float*)d_in[4];
    const float* xemb2 = (const float*)d_in[5];
    const float* ee1   = (const float*)d_in[6];
    const float* ee2   = (const float*)d_in[7];
    const float* w1    = (const float*)d_in[8];
    const float* b1    = (const float*)d_in[9];
    const float* w2    = (const float*)d_in[10];
    const float* b2    = (const float*)d_in[11];
    const float* gamma = (const float*)d_in[12];
    const float* beta  = (const float*)d_in[13];
    const float* fw    = (const float*)d_in[14];
    const float* fb    = (const float*)d_in[15];
    const float* pw1   = (const float*)d_in[16];
    const float* pb1   = (const float*)d_in[17];
    const float* pw2   = (const float*)d_in[18];
    const float* pb2   = (const float*)d_in[19];
    float* out = (float*)d_out;

    float *p_h, *p_agg, *p_hidden, *p_hf, *p_wbuf;
    cudaGetSymbolAddress((void**)&p_h, g_h);
    cudaGetSymbolAddress((void**)&p_agg, g_agg);
    cudaGetSymbolAddress((void**)&p_hidden, g_hidden);
    cudaGetSymbolAddress((void**)&p_hf, g_hf);
    cudaGetSymbolAddress((void**)&p_wbuf, g_wbuf);

    const long long nelem = (long long)NN * EMB;
    const int T = 256;
    const int gNE = (int)((nelem + T - 1) / T);
    const int MB = (NN + 127) / 128;
    const int NB_SCAN = (NN + 1023) / 1024;

    embed_k<<<gNE, T>>>(x, xemb1, xemb2);

    deg_zero_k<<<(NN + T - 1) / T, T>>>();
    deg_count_k<<<(EE + T - 1) / T, T>>>(ei);
    scan1_k<<<NB_SCAN, 256>>>();
    scan2_k<<<1, 32>>>(NB_SCAN);
    scan3_k<<<(NN + T - 1) / T, T>>>();
    fill_k<<<(EE + T - 1) / T, T>>>(ei, ea);

    for (int l = 0; l < LL; l++) {
        const float* ee1l = ee1 + (size_t)l * 6 * EMB;
        const float* ee2l = ee2 + (size_t)l * 3 * EMB;
        ctab_k<<<(18 * EMB + T - 1) / T, T>>>(ee1l, ee2l);
        if (l == 0) gather_k<false><<<(NN + 7) / 8, 256>>>();
        else        gather_k<true><<<(NN + 7) / 8, 256>>>();

        bn_zero_k<<<1, 320>>>();

        round_k<<<(EMB * H2 + T - 1) / T, T>>>(w1 + (size_t)l * EMB * H2, EMB * H2);
        dim3 grid1((H2 + 127) / 128, MB);
        wgemm_k<true, false, true><<<grid1, 256>>>(p_agg, p_wbuf,
                                                   b1 + (size_t)l * H2, p_hidden,
                                                   NN, EMB, H2);
        round_k<<<(EMB * H2 + T - 1) / T, T>>>(w2 + (size_t)l * H2 * EMB, H2 * EMB);
        dim3 grid2((EMB + 127) / 128, MB);
        wgemm_k<false, true, false><<<grid2, 256>>>(p_hidden, p_wbuf,
                                                    b2 + (size_t)l * EMB, p_h,
                                                    NN, H2, EMB);
        bnfin_k<<<1, 320>>>(gamma + (size_t)l * EMB, beta + (size_t)l * EMB);
    }

    bn_apply_k<<<gNE, T>>>();
    round_k<<<(EMB * FEATD + T - 1) / T, T>>>(fw, EMB * FEATD);
    dim3 gridf((FEATD + 127) / 128, MB);
    wgemm_k<false, false, false><<<gridf, 256>>>(p_h, p_wbuf, fb, p_hf,
                                                 NN, EMB, FEATD);

    start_init_k<<<(GG + 1 + T - 1) / T, T>>>();
    bounds_k<<<(NN + T - 1) / T, T>>>(batch);
    pool_g_k<<<GG, FEATD>>>(out);
    pred_k<<<GG, 128>>>(pw1, pb1, pw2, pb2, out);
}